// round 9
// baseline (speedup 1.0000x reference)
#include <cuda_runtime.h>
#include <cuda_fp16.h>
#include <cstdint>

#define KCAP 512
#define DDIM 1024
#define BMAX 16384
#define PAD  520

// ---------------- device scratch (no allocations allowed) ----------------
__device__ __align__(16) float g_At[KCAP * KCAP];   // fp32 0.1*A_diff^T (for k_prep)
// Permuted f16x2 At for k_main: [g(32)][bi(32)][n''(64)] uint2 {kpair g*8+kq, +4}
// bi = q*4 + kq, n = q + 8*n''  (q = n&7, n'' = n>>3)
__device__ __align__(16) uint2 g_AtP[32 * 32 * 64];
__device__ float g_nsp[4 * BMAX];
__device__ float g_agr[BMAX];
__device__ __align__(16) float g_u1[KCAP];
__device__ __align__(16) float g_w1[KCAP];
__device__ float g_sc[2];                            // {1/T_eff, c}

// ---------------- helpers ----------------
__device__ __forceinline__ float blkMax256(float v, float* sc) {
    #pragma unroll
    for (int o = 16; o > 0; o >>= 1) v = fmaxf(v, __shfl_xor_sync(0xffffffffu, v, o));
    if ((threadIdx.x & 31) == 0) sc[threadIdx.x >> 5] = v;
    __syncthreads();
    float r = sc[0];
    #pragma unroll
    for (int i = 1; i < 8; i++) r = fmaxf(r, sc[i]);
    __syncthreads();
    return r;
}
__device__ __forceinline__ float blkSum256(float v, float* sc) {
    #pragma unroll
    for (int o = 16; o > 0; o >>= 1) v += __shfl_xor_sync(0xffffffffu, v, o);
    if ((threadIdx.x & 31) == 0) sc[threadIdx.x >> 5] = v;
    __syncthreads();
    float r = sc[0];
    #pragma unroll
    for (int i = 1; i < 8; i++) r += sc[i];
    __syncthreads();
    return r;
}
// pack two floats to f16x2: first arg -> low half, second -> high half
__device__ __forceinline__ unsigned packhf(float lo, float hi) {
    unsigned r;
    asm("cvt.rn.f16x2.f32 %0, %1, %2;" : "=r"(r) : "f"(hi), "f"(lo));
    return r;
}
__device__ __forceinline__ float lof16(unsigned h) {
    __half2 v = *reinterpret_cast<__half2*>(&h);
    return __low2float(v);
}
__device__ __forceinline__ float hif16(unsigned h) {
    __half2 v = *reinterpret_cast<__half2*>(&h);
    return __high2float(v);
}

__device__ __forceinline__ void cp16(void* dst, const void* src) {
    unsigned s = (unsigned)__cvta_generic_to_shared(dst);
    asm volatile("cp.async.cg.shared.global [%0], [%1], 16;\n" :: "r"(s), "l"(src));
}
__device__ __forceinline__ void cpcommit() { asm volatile("cp.async.commit_group;\n"); }
template <int N>
__device__ __forceinline__ void cpwait() { asm volatile("cp.async.wait_group %0;\n" :: "n"(N)); }

#define MMA_F16(c, a0, a1, a2, a3, b0, b1)                                             \
    asm volatile(                                                                       \
        "mma.sync.aligned.m16n8k16.row.col.f32.f16.f16.f32 "                            \
        "{%0,%1,%2,%3},{%4,%5,%6,%7},{%8,%9},{%0,%1,%2,%3};"                            \
        : "+f"((c)[0]), "+f"((c)[1]), "+f"((c)[2]), "+f"((c)[3])                        \
        : "r"(a0), "r"(a1), "r"(a2), "r"(a3), "r"(b0), "r"(b1))

// ---------------- P0: scalars ----------------
__global__ void k_scalars(const float* __restrict__ lT, const float* __restrict__ lc,
                          const void* __restrict__ tp) {
    if (threadIdx.x == 0) {
        unsigned w = *(const unsigned*)tp;
        float ft = __uint_as_float(w);
        float tempv = (fabsf(ft) > 1e-30f && fabsf(ft) < 1e30f) ? ft : (float)(int)w;
        float T = fminf(fmaxf(expf(lT[0]) * tempv, 0.05f), 10.0f);
        g_sc[0] = 1.0f / T;
        g_sc[1] = fminf(fmaxf(expf(lc[0]), 0.01f), 10.0f);
    }
}

// ---------------- P1: symmetric softmax -> At fp32 + permuted f16x2 ----------------
__global__ void __launch_bounds__(256) k_adiff(const float* __restrict__ A) {
    __shared__ float scr[8];
    __shared__ float col[KCAP];
    const int j = blockIdx.x, tid = threadIdx.x;
    float v0 = 0.5f * (A[j * KCAP + tid]       + A[tid * KCAP + j]);
    float v1 = 0.5f * (A[j * KCAP + tid + 256] + A[(tid + 256) * KCAP + j]);
    float M = blkMax256(fmaxf(v0, v1), scr);
    float e0 = __expf(v0 - M), e1 = __expf(v1 - M);
    float S = blkSum256(e0 + e1, scr);
    float r = 0.1f / S;
    float a0 = e0 * r, a1 = e1 * r;
    g_At[tid * KCAP + j]         = a0;
    g_At[(tid + 256) * KCAP + j] = a1;
    col[tid] = a0; col[tid + 256] = a1;
    __syncthreads();
    if (tid < 128) {
        int g = tid >> 2, kq = tid & 3;
        int p0 = g * 8 + kq;
        int p1 = p0 + 4;
        uint2 v;
        v.x = packhf(col[2 * p0], col[2 * p0 + 1]);
        v.y = packhf(col[2 * p1], col[2 * p1 + 1]);
        int q = j & 7, n2 = j >> 3;
        g_AtP[g * 2048 + (q * 4 + kq) * 64 + n2] = v;
    }
}

// ---------------- P2: fold iteration 0 ----------------
__global__ void __launch_bounds__(256) k_prep(const float* __restrict__ brun) {
    __shared__ float br[KCAP];
    __shared__ float sg[KCAP];
    __shared__ float scr[8];
    const int tid = threadIdx.x;
    const float invT = g_sc[0];
    float v0 = brun[tid], v1 = brun[tid + 256];
    br[tid] = v0; br[tid + 256] = v1;
    float M = blkMax256(fmaxf(v0, v1), scr);
    float e0 = __expf((v0 - M) * invT), e1 = __expf((v1 - M) * invT);
    float S = blkSum256(e0 + e1, scr);
    float is = 1.0f / S;
    sg[tid] = e0 * is; sg[tid + 256] = e1 * is;
    __syncthreads();
    const int j = blockIdx.x * 256 + tid;
    float u = 0.0f, w = 0.0f;
    #pragma unroll 8
    for (int k = 0; k < KCAP; k++) {
        float at = g_At[k * KCAP + j];
        u = fmaf(br[k], at, u);
        w = fmaf(sg[k], at, w);
    }
    g_u1[j] = br[j] + u;
    g_w1[j] = sg[j] + w;
}

// ---------------- P3: fused x@W.T + row sum-of-squares via fp16 2-mma split ----------------
#define SSTRIDE 20
__global__ void __launch_bounds__(256, 2) k_norm(const float* __restrict__ x,
                                                 const float* __restrict__ W, int B) {
    __shared__ unsigned XH[128 * SSTRIDE];
    __shared__ unsigned XL[128 * SSTRIDE];
    __shared__ unsigned WH[128 * SSTRIDE];
    __shared__ float red2[128 * 2];

    const int tid  = threadIdx.x;
    const int lane = tid & 31;
    const int w    = tid >> 5;
    const int mrow = (w & 3) * 32;
    const int ncol = (w >> 2) * 64;
    const int row0 = blockIdx.x * 128;
    const int col0 = blockIdx.y * 128;

    const int srow = tid >> 1;
    const int soff = (tid & 1) * 16;
    const float* xp = x + (size_t)(row0 + srow) * DDIM + soff;
    const float* wp = W + (size_t)(col0 + srow) * DDIM + soff;
    const int sbase = srow * SSTRIDE + (tid & 1) * 8;

    float acc[2][8][4];
    #pragma unroll
    for (int mt = 0; mt < 2; mt++)
        #pragma unroll
        for (int nt = 0; nt < 8; nt++)
            #pragma unroll
            for (int q = 0; q < 4; q++) acc[mt][nt][q] = 0.0f;

    float4 rx[4], rw[4];
    #pragma unroll
    for (int i = 0; i < 4; i++) { rx[i] = *(const float4*)(xp + i * 4); rw[i] = *(const float4*)(wp + i * 4); }

    for (int kt = 0; kt < DDIM / 32; kt++) {
        __syncthreads();
        #pragma unroll
        for (int i = 0; i < 4; i++) {
            float4 v = rx[i];
            unsigned h0 = packhf(v.x, v.y);
            float l0 = v.x - lof16(h0);
            float l1 = v.y - hif16(h0);
            unsigned h1 = packhf(v.z, v.w);
            float l2 = v.z - lof16(h1);
            float l3 = v.w - hif16(h1);
            XH[sbase + i * 2]     = h0;
            XH[sbase + i * 2 + 1] = h1;
            XL[sbase + i * 2]     = packhf(l0, l1);
            XL[sbase + i * 2 + 1] = packhf(l2, l3);
            float4 u = rw[i];
            WH[sbase + i * 2]     = packhf(u.x, u.y);
            WH[sbase + i * 2 + 1] = packhf(u.z, u.w);
        }
        __syncthreads();
        if (kt < DDIM / 32 - 1) {
            const float* xq = xp + (kt + 1) * 32;
            const float* wq = wp + (kt + 1) * 32;
            #pragma unroll
            for (int i = 0; i < 4; i++) { rx[i] = *(const float4*)(xq + i * 4); rw[i] = *(const float4*)(wq + i * 4); }
        }
        #pragma unroll
        for (int c = 0; c < 2; c++) {
            const int kb = c * 8 + (lane & 3);
            unsigned ah[2][4], al[2][4];
            #pragma unroll
            for (int mt = 0; mt < 2; mt++) {
                int ra = (mrow + mt * 16 + (lane >> 2)) * SSTRIDE;
                ah[mt][0] = XH[ra + kb];
                ah[mt][1] = XH[ra + 8 * SSTRIDE + kb];
                ah[mt][2] = XH[ra + kb + 4];
                ah[mt][3] = XH[ra + 8 * SSTRIDE + kb + 4];
                al[mt][0] = XL[ra + kb];
                al[mt][1] = XL[ra + 8 * SSTRIDE + kb];
                al[mt][2] = XL[ra + kb + 4];
                al[mt][3] = XL[ra + 8 * SSTRIDE + kb + 4];
            }
            #pragma unroll
            for (int nt = 0; nt < 8; nt++) {
                int rb = (ncol + nt * 8 + (lane >> 2)) * SSTRIDE;
                unsigned bh0 = WH[rb + kb], bh1 = WH[rb + kb + 4];
                #pragma unroll
                for (int mt = 0; mt < 2; mt++) {
                    MMA_F16(acc[mt][nt], ah[mt][0], ah[mt][1], ah[mt][2], ah[mt][3], bh0, bh1);
                    MMA_F16(acc[mt][nt], al[mt][0], al[mt][1], al[mt][2], al[mt][3], bh0, bh1);
                }
            }
        }
    }

    #pragma unroll
    for (int mt = 0; mt < 2; mt++) {
        #pragma unroll
        for (int h = 0; h < 2; h++) {
            float s = 0.0f;
            #pragma unroll
            for (int nt = 0; nt < 8; nt++) {
                float a = acc[mt][nt][2 * h], b = acc[mt][nt][2 * h + 1];
                s = fmaf(a, a, fmaf(b, b, s));
            }
            s += __shfl_xor_sync(0xffffffffu, s, 1);
            s += __shfl_xor_sync(0xffffffffu, s, 2);
            if ((lane & 3) == 0) {
                int rloc = mrow + mt * 16 + (lane >> 2) + h * 8;
                red2[rloc * 2 + (w >> 2)] = s;
            }
        }
    }
    __syncthreads();
    if (tid < 128) {
        float s = red2[tid * 2] + red2[tid * 2 + 1];
        g_nsp[(size_t)blockIdx.y * B + row0 + tid] = s;
    }
}

// ---------------- P4: agreement ----------------
__global__ void k_agree(int B) {
    int i = blockIdx.x * 256 + threadIdx.x;
    if (i < B) {
        float c = g_sc[1];
        float ns = g_nsp[i] + g_nsp[B + i] + g_nsp[2 * B + i] + g_nsp[3 * B + i];
        ns = fmaxf(ns, 1e-10f);
        float sc2 = c * ns / (1.0f + c * ns);
        g_agr[i] = sc2 * sqrtf(ns);
    }
}

// ---------------- MAIN: 32 rows/block, 2 blocks/SM, fp16 2-mma diffusion GEMM ----------------
// Slab per kc (k16 = one g-group): 32 bi x 66 uint2 (64 data + 2 pad) = 2112 uint2 = 16.9KB.
// smem: b_s[32][520] f32 (66560B) | slab 2x2112 uint2 (33792B) | red[512] | agrs[32]
#define GS2 2112
#define SMEM_MAIN_BYTES (32 * PAD * 4 + 2 * GS2 * 8 + 512 * 4 + 32 * 4)

__global__ void __launch_bounds__(512, 2) k_main(float* __restrict__ out) {
    extern __shared__ float sm[];
    float* b_s   = sm;                                  // [32][PAD]
    uint2* slab  = (uint2*)(sm + 32 * PAD);             // 2 x GS2
    float* red   = (float*)(slab + 2 * GS2);            // [512]
    float* agrs  = red + 512;                           // [32]

    const int tid  = threadIdx.x;
    const int lane = tid & 31;
    const int wrp  = tid >> 5;               // 0..15
    const int rbase = (wrp & 1) * 16;        // 2 row stripes of 16
    const int cs    = wrp >> 1;              // 0..7 col stripes of 64
    const int nbase = cs * 64;
    const int n2b   = cs * 8;                // n'' base (8 uint2 per warp)
    const int row0 = blockIdx.x * 32;
    const float invT = g_sc[0];

    const int r   = tid >> 4;                // 0..31
    const int t16 = tid & 15;
    float* base = b_s + r * PAD + t16 * 4;

    if (tid < 32) agrs[tid] = g_agr[row0 + tid];
    float uj = g_u1[tid & 511];
    float wj = g_w1[tid & 511];
    __syncthreads();
    #pragma unroll 4
    for (int r2 = 0; r2 < 32; r2++)
        b_s[r2 * PAD + tid] = fmaf(agrs[r2], wj, uj);
    __syncthreads();

    for (int it = 0; it < 4; it++) {
        // prefetch g=0 slab (1024 16B chunks, 2 per thread) — overlaps with softmax
        {
            #pragma unroll
            for (int q = 0; q < 2; q++) {
                int c = tid + q * 512;
                int bi = c >> 5, off = (c & 31) * 2;
                cp16(slab + bi * 66 + off, g_AtP + bi * 64 + off);
            }
            cpcommit();
        }

        // ---- b += a * softmax(b/T) ----  (16 threads per row, 32 cols each)
        float mx = -3.4e38f;
        #pragma unroll
        for (int j = 0; j < 8; j++) {
            float4 v = *(const float4*)(base + j * 64);
            mx = fmaxf(mx, fmaxf(fmaxf(v.x, v.y), fmaxf(v.z, v.w)));
        }
        red[tid] = mx; __syncthreads();
        float m = red[r * 16];
        #pragma unroll
        for (int q = 1; q < 16; q++) m = fmaxf(m, red[r * 16 + q]);
        __syncthreads();
        float s = 0.0f;
        #pragma unroll
        for (int j = 0; j < 8; j++) {
            float4 v = *(const float4*)(base + j * 64);
            s += __expf((v.x - m) * invT) + __expf((v.y - m) * invT)
               + __expf((v.z - m) * invT) + __expf((v.w - m) * invT);
        }
        red[tid] = s; __syncthreads();
        float S = red[r * 16];
        #pragma unroll
        for (int q = 1; q < 16; q++) S += red[r * 16 + q];
        float aS = agrs[r] / S;
        #pragma unroll
        for (int j = 0; j < 8; j++) {
            float4 v = *(const float4*)(base + j * 64);
            v.x = fmaf(aS, __expf((v.x - m) * invT), v.x);
            v.y = fmaf(aS, __expf((v.y - m) * invT), v.y);
            v.z = fmaf(aS, __expf((v.z - m) * invT), v.z);
            v.w = fmaf(aS, __expf((v.w - m) * invT), v.w);
            *(float4*)(base + j * 64) = v;
        }
        __syncthreads();

        // ---- d = b @ AtH via fp16 2-mma split, k16 chunks ----
        float acc[8][4];
        #pragma unroll
        for (int t = 0; t < 8; t++)
            #pragma unroll
            for (int q = 0; q < 4; q++) acc[t][q] = 0.0f;

        for (int g = 0; g < 32; g++) {
            if (g < 31) {
                const uint2* src = g_AtP + (g + 1) * 2048;
                uint2* dst = slab + ((g + 1) & 1) * GS2;
                #pragma unroll
                for (int q = 0; q < 2; q++) {
                    int c = tid + q * 512;
                    int bi = c >> 5, off = (c & 31) * 2;
                    cp16(dst + bi * 66 + off, src + bi * 64 + off);
                }
                cpcommit();
                cpwait<1>();
            } else {
                cpwait<0>();
            }
            __syncthreads();

            const uint2* sB = slab + (g & 1) * GS2;
            const int k0 = g * 16;

            // A fragments: rows rbase+(lane>>2), +8; k pairs (lane&3)*2, +8
            const float* ap = b_s + (rbase + (lane >> 2)) * PAD + k0 + (lane & 3) * 2;
            float2 v00 = *(const float2*)ap;
            float2 v10 = *(const float2*)(ap + 8 * PAD);
            float2 v01 = *(const float2*)(ap + 8);
            float2 v11 = *(const float2*)(ap + 8 * PAD + 8);
            unsigned ah0 = packhf(v00.x, v00.y);
            unsigned ah1 = packhf(v10.x, v10.y);
            unsigned ah2 = packhf(v01.x, v01.y);
            unsigned ah3 = packhf(v11.x, v11.y);
            unsigned al0 = packhf(v00.x - lof16(ah0), v00.y - hif16(ah0));
            unsigned al1 = packhf(v10.x - lof16(ah1), v10.y - hif16(ah1));
            unsigned al2 = packhf(v01.x - lof16(ah2), v01.y - hif16(ah2));
            unsigned al3 = packhf(v11.x - lof16(ah3), v11.y - hif16(ah3));

            // B fragments: block bi = lane, 8 consecutive uint2 from n2b (4 uint4 loads)
            const uint4* bp = (const uint4*)(sB + lane * 66 + n2b);
            #pragma unroll
            for (int jj = 0; jj < 4; jj++) {
                uint4 bv = bp[jj];   // {b0(t=2jj), b1(t=2jj), b0(t=2jj+1), b1(t=2jj+1)}
                MMA_F16(acc[2 * jj],     ah0, ah1, ah2, ah3, bv.x, bv.y);
                MMA_F16(acc[2 * jj],     al0, al1, al2, al3, bv.x, bv.y);
                MMA_F16(acc[2 * jj + 1], ah0, ah1, ah2, ah3, bv.z, bv.w);
                MMA_F16(acc[2 * jj + 1], al0, al1, al2, al3, bv.z, bv.w);
            }
            __syncthreads();
        }

        // ---- b += d ----
        float* ep = b_s + (rbase + (lane >> 2)) * PAD + nbase + 2 * (lane & 3);
        #pragma unroll
        for (int t = 0; t < 8; t++) {
            float* p = ep + t * 8;
            p[0]           += acc[t][0];
            p[1]           += acc[t][1];
            p[8 * PAD]     += acc[t][2];
            p[8 * PAD + 1] += acc[t][3];
        }
        __syncthreads();
    }

    // ---- theta = softmax(b/T) -> out ----
    {
        float mx = -3.4e38f;
        #pragma unroll
        for (int j = 0; j < 8; j++) {
            float4 v = *(const float4*)(base + j * 64);
            mx = fmaxf(mx, fmaxf(fmaxf(v.x, v.y), fmaxf(v.z, v.w)));
        }
        red[tid] = mx; __syncthreads();
        float m = red[r * 16];
        #pragma unroll
        for (int q = 1; q < 16; q++) m = fmaxf(m, red[r * 16 + q]);
        __syncthreads();
        float s = 0.0f;
        #pragma unroll
        for (int j = 0; j < 8; j++) {
            float4 v = *(const float4*)(base + j * 64);
            s += __expf((v.x - m) * invT) + __expf((v.y - m) * invT)
               + __expf((v.z - m) * invT) + __expf((v.w - m) * invT);
        }
        red[tid] = s; __syncthreads();
        float S = red[r * 16];
        #pragma unroll
        for (int q = 1; q < 16; q++) S += red[r * 16 + q];
        float iS = 1.0f / S;
        float* op = out + (size_t)(row0 + r) * KCAP + t16 * 4;
        #pragma unroll
        for (int j = 0; j < 8; j++) {
            float4 v = *(const float4*)(base + j * 64);
            float4 o;
            o.x = __expf((v.x - m) * invT) * iS;
            o.y = __expf((v.y - m) * invT) * iS;
            o.z = __expf((v.z - m) * invT) * iS;
            o.w = __expf((v.w - m) * invT) * iS;
            *(float4*)(op + j * 64) = o;
        }
    }
}

// ---------------- launcher ----------------
extern "C" void kernel_launch(void* const* d_in, const int* in_sizes, int n_in,
                              void* d_out, int out_size) {
    const float* x    = (const float*)d_in[0];
    const float* W    = (const float*)d_in[1];
    const float* A    = (const float*)d_in[2];
    const float* lT   = (const float*)d_in[3];
    const float* lc   = (const float*)d_in[4];
    const float* brun = (const float*)d_in[5];
    const void*  temp = d_in[6];
    const int B = in_sizes[0] / DDIM;   // 16384

    cudaFuncSetAttribute(k_main, cudaFuncAttributeMaxDynamicSharedMemorySize,
                         SMEM_MAIN_BYTES);

    k_scalars<<<1, 32>>>(lT, lc, temp);
    k_adiff<<<KCAP, 256>>>(A);
    k_prep<<<2, 256>>>(brun);
    k_norm<<<dim3(B / 128, 4), 256>>>(x, W, B);
    k_agree<<<(B + 255) / 256, 256>>>(B);
    k_main<<<B / 32, 512, SMEM_MAIN_BYTES>>>((float*)d_out);
}

// round 10
// speedup vs baseline: 1.3330x; 1.3330x over previous
#include <cuda_runtime.h>
#include <cuda_fp16.h>
#include <cstdint>

#define KCAP 512
#define DDIM 1024
#define BMAX 16384
#define PAD  520

// ---------------- device scratch (no allocations allowed) ----------------
__device__ __align__(16) float g_At[KCAP * KCAP];   // fp32 0.1*A_diff^T (for k_prep)
// Permuted f16x2 At for k_main: [g(32)][bi(32)][n''(64)] uint2 {kpair g*8+kq, +4}
// bi = q*4 + kq, n = q + 8*n''  (q = n&7, n'' = n>>3)
__device__ __align__(16) uint2 g_AtP[32 * 32 * 64];
__device__ float g_nsp[4 * BMAX];
__device__ float g_agr[BMAX];
__device__ __align__(16) float g_u1[KCAP];
__device__ __align__(16) float g_w1[KCAP];
__device__ float g_sc[2];                            // {1/T_eff, c}

// ---------------- helpers ----------------
__device__ __forceinline__ float blkMax256(float v, float* sc) {
    #pragma unroll
    for (int o = 16; o > 0; o >>= 1) v = fmaxf(v, __shfl_xor_sync(0xffffffffu, v, o));
    if ((threadIdx.x & 31) == 0) sc[threadIdx.x >> 5] = v;
    __syncthreads();
    float r = sc[0];
    #pragma unroll
    for (int i = 1; i < 8; i++) r = fmaxf(r, sc[i]);
    __syncthreads();
    return r;
}
__device__ __forceinline__ float blkSum256(float v, float* sc) {
    #pragma unroll
    for (int o = 16; o > 0; o >>= 1) v += __shfl_xor_sync(0xffffffffu, v, o);
    if ((threadIdx.x & 31) == 0) sc[threadIdx.x >> 5] = v;
    __syncthreads();
    float r = sc[0];
    #pragma unroll
    for (int i = 1; i < 8; i++) r += sc[i];
    __syncthreads();
    return r;
}
// pack two floats to f16x2: first arg -> low half, second -> high half
__device__ __forceinline__ unsigned packhf(float lo, float hi) {
    unsigned r;
    asm("cvt.rn.f16x2.f32 %0, %1, %2;" : "=r"(r) : "f"(hi), "f"(lo));
    return r;
}

__device__ __forceinline__ void cp16(void* dst, const void* src) {
    unsigned s = (unsigned)__cvta_generic_to_shared(dst);
    asm volatile("cp.async.cg.shared.global [%0], [%1], 16;\n" :: "r"(s), "l"(src));
}
__device__ __forceinline__ void cpcommit() { asm volatile("cp.async.commit_group;\n"); }
template <int N>
__device__ __forceinline__ void cpwait() { asm volatile("cp.async.wait_group %0;\n" :: "n"(N)); }

#define MMA_F16(c, a0, a1, a2, a3, b0, b1)                                             \
    asm volatile(                                                                       \
        "mma.sync.aligned.m16n8k16.row.col.f32.f16.f16.f32 "                            \
        "{%0,%1,%2,%3},{%4,%5,%6,%7},{%8,%9},{%0,%1,%2,%3};"                            \
        : "+f"((c)[0]), "+f"((c)[1]), "+f"((c)[2]), "+f"((c)[3])                        \
        : "r"(a0), "r"(a1), "r"(a2), "r"(a3), "r"(b0), "r"(b1))

// ---------------- P0: scalars ----------------
__global__ void k_scalars(const float* __restrict__ lT, const float* __restrict__ lc,
                          const void* __restrict__ tp) {
    if (threadIdx.x == 0) {
        unsigned w = *(const unsigned*)tp;
        float ft = __uint_as_float(w);
        float tempv = (fabsf(ft) > 1e-30f && fabsf(ft) < 1e30f) ? ft : (float)(int)w;
        float T = fminf(fmaxf(expf(lT[0]) * tempv, 0.05f), 10.0f);
        g_sc[0] = 1.0f / T;
        g_sc[1] = fminf(fmaxf(expf(lc[0]), 0.01f), 10.0f);
    }
}

// ---------------- P1: symmetric softmax -> At fp32 + permuted f16x2 ----------------
__global__ void __launch_bounds__(256) k_adiff(const float* __restrict__ A) {
    __shared__ float scr[8];
    __shared__ float col[KCAP];
    const int j = blockIdx.x, tid = threadIdx.x;
    float v0 = 0.5f * (A[j * KCAP + tid]       + A[tid * KCAP + j]);
    float v1 = 0.5f * (A[j * KCAP + tid + 256] + A[(tid + 256) * KCAP + j]);
    float M = blkMax256(fmaxf(v0, v1), scr);
    float e0 = __expf(v0 - M), e1 = __expf(v1 - M);
    float S = blkSum256(e0 + e1, scr);
    float r = 0.1f / S;
    float a0 = e0 * r, a1 = e1 * r;
    g_At[tid * KCAP + j]         = a0;
    g_At[(tid + 256) * KCAP + j] = a1;
    col[tid] = a0; col[tid + 256] = a1;
    __syncthreads();
    if (tid < 128) {
        int g = tid >> 2, kq = tid & 3;
        int p0 = g * 8 + kq;
        int p1 = p0 + 4;
        uint2 v;
        v.x = packhf(col[2 * p0], col[2 * p0 + 1]);
        v.y = packhf(col[2 * p1], col[2 * p1 + 1]);
        int q = j & 7, n2 = j >> 3;
        g_AtP[g * 2048 + (q * 4 + kq) * 64 + n2] = v;
    }
}

// ---------------- P2: fold iteration 0 ----------------
__global__ void __launch_bounds__(256) k_prep(const float* __restrict__ brun) {
    __shared__ float br[KCAP];
    __shared__ float sg[KCAP];
    __shared__ float scr[8];
    const int tid = threadIdx.x;
    const float invT = g_sc[0];
    float v0 = brun[tid], v1 = brun[tid + 256];
    br[tid] = v0; br[tid + 256] = v1;
    float M = blkMax256(fmaxf(v0, v1), scr);
    float e0 = __expf((v0 - M) * invT), e1 = __expf((v1 - M) * invT);
    float S = blkSum256(e0 + e1, scr);
    float is = 1.0f / S;
    sg[tid] = e0 * is; sg[tid + 256] = e1 * is;
    __syncthreads();
    const int j = blockIdx.x * 256 + tid;
    float u = 0.0f, w = 0.0f;
    #pragma unroll 8
    for (int k = 0; k < KCAP; k++) {
        float at = g_At[k * KCAP + j];
        u = fmaf(br[k], at, u);
        w = fmaf(sg[k], at, w);
    }
    g_u1[j] = br[j] + u;
    g_w1[j] = sg[j] + w;
}

// ---------------- P3: fused x@W.T + row sum-of-squares, single fp16 mma ----------------
#define SSTRIDE 20
__global__ void __launch_bounds__(256, 2) k_norm(const float* __restrict__ x,
                                                 const float* __restrict__ W, int B) {
    __shared__ unsigned XH[128 * SSTRIDE];
    __shared__ unsigned WH[128 * SSTRIDE];
    __shared__ float red2[128 * 2];

    const int tid  = threadIdx.x;
    const int lane = tid & 31;
    const int w    = tid >> 5;
    const int mrow = (w & 3) * 32;
    const int ncol = (w >> 2) * 64;
    const int row0 = blockIdx.x * 128;
    const int col0 = blockIdx.y * 128;

    const int srow = tid >> 1;
    const int soff = (tid & 1) * 16;
    const float* xp = x + (size_t)(row0 + srow) * DDIM + soff;
    const float* wp = W + (size_t)(col0 + srow) * DDIM + soff;
    const int sbase = srow * SSTRIDE + (tid & 1) * 8;

    float acc[2][8][4];
    #pragma unroll
    for (int mt = 0; mt < 2; mt++)
        #pragma unroll
        for (int nt = 0; nt < 8; nt++)
            #pragma unroll
            for (int q = 0; q < 4; q++) acc[mt][nt][q] = 0.0f;

    float4 rx[4], rw[4];
    #pragma unroll
    for (int i = 0; i < 4; i++) { rx[i] = *(const float4*)(xp + i * 4); rw[i] = *(const float4*)(wp + i * 4); }

    for (int kt = 0; kt < DDIM / 32; kt++) {
        __syncthreads();
        #pragma unroll
        for (int i = 0; i < 4; i++) {
            float4 v = rx[i];
            XH[sbase + i * 2]     = packhf(v.x, v.y);
            XH[sbase + i * 2 + 1] = packhf(v.z, v.w);
            float4 u = rw[i];
            WH[sbase + i * 2]     = packhf(u.x, u.y);
            WH[sbase + i * 2 + 1] = packhf(u.z, u.w);
        }
        __syncthreads();
        if (kt < DDIM / 32 - 1) {
            const float* xq = xp + (kt + 1) * 32;
            const float* wq = wp + (kt + 1) * 32;
            #pragma unroll
            for (int i = 0; i < 4; i++) { rx[i] = *(const float4*)(xq + i * 4); rw[i] = *(const float4*)(wq + i * 4); }
        }
        #pragma unroll
        for (int c = 0; c < 2; c++) {
            const int kb = c * 8 + (lane & 3);
            unsigned ah[2][4];
            #pragma unroll
            for (int mt = 0; mt < 2; mt++) {
                int ra = (mrow + mt * 16 + (lane >> 2)) * SSTRIDE;
                ah[mt][0] = XH[ra + kb];
                ah[mt][1] = XH[ra + 8 * SSTRIDE + kb];
                ah[mt][2] = XH[ra + kb + 4];
                ah[mt][3] = XH[ra + 8 * SSTRIDE + kb + 4];
            }
            #pragma unroll
            for (int nt = 0; nt < 8; nt++) {
                int rb = (ncol + nt * 8 + (lane >> 2)) * SSTRIDE;
                unsigned bh0 = WH[rb + kb], bh1 = WH[rb + kb + 4];
                #pragma unroll
                for (int mt = 0; mt < 2; mt++) {
                    MMA_F16(acc[mt][nt], ah[mt][0], ah[mt][1], ah[mt][2], ah[mt][3], bh0, bh1);
                }
            }
        }
    }

    #pragma unroll
    for (int mt = 0; mt < 2; mt++) {
        #pragma unroll
        for (int h = 0; h < 2; h++) {
            float s = 0.0f;
            #pragma unroll
            for (int nt = 0; nt < 8; nt++) {
                float a = acc[mt][nt][2 * h], b = acc[mt][nt][2 * h + 1];
                s = fmaf(a, a, fmaf(b, b, s));
            }
            s += __shfl_xor_sync(0xffffffffu, s, 1);
            s += __shfl_xor_sync(0xffffffffu, s, 2);
            if ((lane & 3) == 0) {
                int rloc = mrow + mt * 16 + (lane >> 2) + h * 8;
                red2[rloc * 2 + (w >> 2)] = s;
            }
        }
    }
    __syncthreads();
    if (tid < 128) {
        float s = red2[tid * 2] + red2[tid * 2 + 1];
        g_nsp[(size_t)blockIdx.y * B + row0 + tid] = s;
    }
}

// ---------------- P4: agreement ----------------
__global__ void k_agree(int B) {
    int i = blockIdx.x * 256 + threadIdx.x;
    if (i < B) {
        float c = g_sc[1];
        float ns = g_nsp[i] + g_nsp[B + i] + g_nsp[2 * B + i] + g_nsp[3 * B + i];
        ns = fmaxf(ns, 1e-10f);
        float sc2 = c * ns / (1.0f + c * ns);
        g_agr[i] = sc2 * sqrtf(ns);
    }
}

// ---------------- MAIN: 64 rows/block, single-fp16 diffusion GEMM ----------------
// Slab per kc (k32): 2 g-groups x 32 blocks x 66 uint2 = 4224 uint2 = 33.8KB; 2 buffers.
#define GSLAB 2112
#define SLABU (2 * GSLAB)
#define SMEM_MAIN_BYTES (64 * PAD * 4 + 2 * SLABU * 8 + 512 * 4 + 64 * 4)

__global__ void __launch_bounds__(512, 1) k_main(float* __restrict__ out) {
    extern __shared__ float sm[];
    float* b_s   = sm;                                  // [64][PAD]
    uint2* slab  = (uint2*)(sm + 64 * PAD);             // 2 x SLABU
    float* red   = (float*)(slab + 2 * SLABU);          // [512]
    float* agrs  = red + 512;                           // [64]

    const int tid  = threadIdx.x;
    const int lane = tid & 31;
    const int wrp  = tid >> 5;               // 0..15
    const int rbase = (wrp & 3) * 16;        // row stripe
    const int nbase = (wrp >> 2) * 128;      // col stripe
    const int n2b   = (wrp >> 2) * 16;       // n'' base
    const int row0 = blockIdx.x * 64;
    const float invT = g_sc[0];

    const int r  = tid >> 3;                 // 0..63
    const int t8 = tid & 7;
    float* base = b_s + r * PAD + t8 * 4;

    if (tid < 64) agrs[tid] = g_agr[row0 + tid];
    float uj = g_u1[tid & 511];
    float wj = g_w1[tid & 511];
    __syncthreads();
    #pragma unroll 8
    for (int r2 = 0; r2 < 64; r2++)
        b_s[r2 * PAD + tid] = fmaf(agrs[r2], wj, uj);
    __syncthreads();

    for (int it = 0; it < 4; it++) {
        // prefetch kc=0 slab — overlaps with softmax
        {
            #pragma unroll
            for (int q = 0; q < 4; q++) {
                int c = tid + q * 512;
                int gg = c >> 10, bi = (c >> 5) & 31, off = (c & 31) * 2;
                cp16(slab + gg * GSLAB + bi * 66 + off,
                     g_AtP + gg * 2048 + bi * 64 + off);
            }
            cpcommit();
        }

        // ---- b += a * softmax(b/T) ----
        float mx = -3.4e38f;
        #pragma unroll
        for (int j = 0; j < 16; j++) {
            float4 v = *(const float4*)(base + j * 32);
            mx = fmaxf(mx, fmaxf(fmaxf(v.x, v.y), fmaxf(v.z, v.w)));
        }
        red[tid] = mx; __syncthreads();
        float m = red[r * 8];
        #pragma unroll
        for (int q = 1; q < 8; q++) m = fmaxf(m, red[r * 8 + q]);
        __syncthreads();
        float s = 0.0f;
        #pragma unroll
        for (int j = 0; j < 16; j++) {
            float4 v = *(const float4*)(base + j * 32);
            s += __expf((v.x - m) * invT) + __expf((v.y - m) * invT)
               + __expf((v.z - m) * invT) + __expf((v.w - m) * invT);
        }
        red[tid] = s; __syncthreads();
        float S = red[r * 8];
        #pragma unroll
        for (int q = 1; q < 8; q++) S += red[r * 8 + q];
        float aS = agrs[r] / S;
        #pragma unroll
        for (int j = 0; j < 16; j++) {
            float4 v = *(const float4*)(base + j * 32);
            v.x = fmaf(aS, __expf((v.x - m) * invT), v.x);
            v.y = fmaf(aS, __expf((v.y - m) * invT), v.y);
            v.z = fmaf(aS, __expf((v.z - m) * invT), v.z);
            v.w = fmaf(aS, __expf((v.w - m) * invT), v.w);
            *(float4*)(base + j * 32) = v;
        }
        __syncthreads();

        // ---- d = b @ AtH, single fp16 mma ----
        float acc[16][4];
        #pragma unroll
        for (int t = 0; t < 16; t++)
            #pragma unroll
            for (int q = 0; q < 4; q++) acc[t][q] = 0.0f;

        for (int kc = 0; kc < 16; kc++) {
            if (kc < 15) {
                const uint2* src = g_AtP + (kc + 1) * 2 * 2048;
                uint2* dst = slab + ((kc + 1) & 1) * SLABU;
                #pragma unroll
                for (int q = 0; q < 4; q++) {
                    int c = tid + q * 512;
                    int gg = c >> 10, bi = (c >> 5) & 31, off = (c & 31) * 2;
                    cp16(dst + gg * GSLAB + bi * 66 + off,
                         src + gg * 2048 + bi * 64 + off);
                }
                cpcommit();
                cpwait<1>();
            } else {
                cpwait<0>();
            }
            __syncthreads();

            const uint2* sB = slab + (kc & 1) * SLABU;

            #pragma unroll
            for (int g = 0; g < 2; g++) {
                const int k0 = kc * 32 + g * 16;
                // A fragments: rows rbase+(lane>>2), +8; k pairs (lane&3)*2, +8
                const float* ap = b_s + (rbase + (lane >> 2)) * PAD + k0 + (lane & 3) * 2;
                float2 v00 = *(const float2*)ap;
                float2 v10 = *(const float2*)(ap + 8 * PAD);
                float2 v01 = *(const float2*)(ap + 8);
                float2 v11 = *(const float2*)(ap + 8 * PAD + 8);
                unsigned ah0 = packhf(v00.x, v00.y);
                unsigned ah1 = packhf(v10.x, v10.y);
                unsigned ah2 = packhf(v01.x, v01.y);
                unsigned ah3 = packhf(v11.x, v11.y);

                // B fragments: block bi = lane, 16 consecutive uint2 from n2b
                const uint4* bp = (const uint4*)(sB + g * GSLAB + lane * 66 + n2b);
                #pragma unroll
                for (int jj = 0; jj < 8; jj++) {
                    uint4 bv = bp[jj];   // {b0(t=2jj), b1(t=2jj), b0(t=2jj+1), b1(t=2jj+1)}
                    MMA_F16(acc[2 * jj],     ah0, ah1, ah2, ah3, bv.x, bv.y);
                    MMA_F16(acc[2 * jj + 1], ah0, ah1, ah2, ah3, bv.z, bv.w);
                }
            }
            __syncthreads();
        }

        // ---- b += d ----
        float* ep = b_s + (rbase + (lane >> 2)) * PAD + nbase + 2 * (lane & 3);
        #pragma unroll
        for (int t = 0; t < 16; t++) {
            float* p = ep + t * 8;
            p[0]           += acc[t][0];
            p[1]           += acc[t][1];
            p[8 * PAD]     += acc[t][2];
            p[8 * PAD + 1] += acc[t][3];
        }
        __syncthreads();
    }

    // ---- theta = softmax(b/T) -> out ----
    {
        float mx = -3.4e38f;
        #pragma unroll
        for (int j = 0; j < 16; j++) {
            float4 v = *(const float4*)(base + j * 32);
            mx = fmaxf(mx, fmaxf(fmaxf(v.x, v.y), fmaxf(v.z, v.w)));
        }
        red[tid] = mx; __syncthreads();
        float m = red[r * 8];
        #pragma unroll
        for (int q = 1; q < 8; q++) m = fmaxf(m, red[r * 8 + q]);
        __syncthreads();
        float s = 0.0f;
        #pragma unroll
        for (int j = 0; j < 16; j++) {
            float4 v = *(const float4*)(base + j * 32);
            s += __expf((v.x - m) * invT) + __expf((v.y - m) * invT)
               + __expf((v.z - m) * invT) + __expf((v.w - m) * invT);
        }
        red[tid] = s; __syncthreads();
        float S = red[r * 8];
        #pragma unroll
        for (int q = 1; q < 8; q++) S += red[r * 8 + q];
        float iS = 1.0f / S;
        float* op = out + (size_t)(row0 + r) * KCAP + t8 * 4;
        #pragma unroll
        for (int j = 0; j < 16; j++) {
            float4 v = *(const float4*)(base + j * 32);
            float4 o;
            o.x = __expf((v.x - m) * invT) * iS;
            o.y = __expf((v.y - m) * invT) * iS;
            o.z = __expf((v.z - m) * invT) * iS;
            o.w = __expf((v.w - m) * invT) * iS;
            *(float4*)(op + j * 32) = o;
        }
    }
}

// ---------------- launcher ----------------
extern "C" void kernel_launch(void* const* d_in, const int* in_sizes, int n_in,
                              void* d_out, int out_size) {
    const float* x    = (const float*)d_in[0];
    const float* W    = (const float*)d_in[1];
    const float* A    = (const float*)d_in[2];
    const float* lT   = (const float*)d_in[3];
    const float* lc   = (const float*)d_in[4];
    const float* brun = (const float*)d_in[5];
    const void*  temp = d_in[6];
    const int B = in_sizes[0] / DDIM;   // 16384

    cudaFuncSetAttribute(k_main, cudaFuncAttributeMaxDynamicSharedMemorySize,
                         SMEM_MAIN_BYTES);

    k_scalars<<<1, 32>>>(lT, lc, temp);
    k_adiff<<<KCAP, 256>>>(A);
    k_prep<<<2, 256>>>(brun);
    k_norm<<<dim3(B / 128, 4), 256>>>(x, W, B);
    k_agree<<<(B + 255) / 256, 256>>>(B);
    k_main<<<B / 64, 512, SMEM_MAIN_BYTES>>>((float*)d_out);
}

// round 11
// speedup vs baseline: 1.6429x; 1.2325x over previous
#include <cuda_runtime.h>
#include <cuda_fp16.h>
#include <cstdint>

#define KCAP 512
#define DDIM 1024
#define BMAX 16384
#define PAD  520

// ---------------- device scratch (no allocations allowed) ----------------
__device__ __align__(16) float g_At[KCAP * KCAP];   // fp32 0.1*A_diff^T (for k_prep)
// Lane-major f16 At for k_main B fragments:
// uint idx = (((gg*16 + w)*2 + jj)*32 + lane)*4 + comp
//   gg = k16 chunk (0..31), w = warp n-stripe (0..15), jj = tile pair (0..1),
//   lane: (lane>>2) = n-offset in n8 tile, (lane&3) = kquad
//   comp = tpar*2 + {0:b0, 1:b1}; tile t = jj*2 + tpar; n = w*32 + t*8 + (lane>>2)
//   b0 = {At[k0,n], At[k0+1,n]}, b1 = {At[k0+8,n], At[k0+9,n]}, k0 = gg*16 + 2*(lane&3)
__device__ __align__(16) unsigned g_AtB[32 * 16 * 2 * 32 * 4];
__device__ float g_nsp[4 * BMAX];
__device__ float g_agr[BMAX];
__device__ __align__(16) float g_u1[KCAP];
__device__ __align__(16) float g_w1[KCAP];
__device__ float g_sc[2];                            // {1/T_eff, c}

// ---------------- helpers ----------------
__device__ __forceinline__ float blkMax256(float v, float* sc) {
    #pragma unroll
    for (int o = 16; o > 0; o >>= 1) v = fmaxf(v, __shfl_xor_sync(0xffffffffu, v, o));
    if ((threadIdx.x & 31) == 0) sc[threadIdx.x >> 5] = v;
    __syncthreads();
    float r = sc[0];
    #pragma unroll
    for (int i = 1; i < 8; i++) r = fmaxf(r, sc[i]);
    __syncthreads();
    return r;
}
__device__ __forceinline__ float blkSum256(float v, float* sc) {
    #pragma unroll
    for (int o = 16; o > 0; o >>= 1) v += __shfl_xor_sync(0xffffffffu, v, o);
    if ((threadIdx.x & 31) == 0) sc[threadIdx.x >> 5] = v;
    __syncthreads();
    float r = sc[0];
    #pragma unroll
    for (int i = 1; i < 8; i++) r += sc[i];
    __syncthreads();
    return r;
}
// pack two floats to f16x2: first arg -> low half, second -> high half
__device__ __forceinline__ unsigned packhf(float lo, float hi) {
    unsigned r;
    asm("cvt.rn.f16x2.f32 %0, %1, %2;" : "=r"(r) : "f"(hi), "f"(lo));
    return r;
}

#define MMA_F16(c, a0, a1, a2, a3, b0, b1)                                             \
    asm volatile(                                                                       \
        "mma.sync.aligned.m16n8k16.row.col.f32.f16.f16.f32 "                            \
        "{%0,%1,%2,%3},{%4,%5,%6,%7},{%8,%9},{%0,%1,%2,%3};"                            \
        : "+f"((c)[0]), "+f"((c)[1]), "+f"((c)[2]), "+f"((c)[3])                        \
        : "r"(a0), "r"(a1), "r"(a2), "r"(a3), "r"(b0), "r"(b1))

// ---------------- P0: scalars ----------------
__global__ void k_scalars(const float* __restrict__ lT, const float* __restrict__ lc,
                          const void* __restrict__ tp) {
    if (threadIdx.x == 0) {
        unsigned w = *(const unsigned*)tp;
        float ft = __uint_as_float(w);
        float tempv = (fabsf(ft) > 1e-30f && fabsf(ft) < 1e30f) ? ft : (float)(int)w;
        float T = fminf(fmaxf(expf(lT[0]) * tempv, 0.05f), 10.0f);
        g_sc[0] = 1.0f / T;
        g_sc[1] = fminf(fmaxf(expf(lc[0]), 0.01f), 10.0f);
    }
}

// ---------------- P1: symmetric softmax -> At fp32 + lane-major f16 ----------------
__global__ void __launch_bounds__(256) k_adiff(const float* __restrict__ A) {
    __shared__ float scr[8];
    __shared__ float col[KCAP];
    const int j = blockIdx.x, tid = threadIdx.x;
    float v0 = 0.5f * (A[j * KCAP + tid]       + A[tid * KCAP + j]);
    float v1 = 0.5f * (A[j * KCAP + tid + 256] + A[(tid + 256) * KCAP + j]);
    float M = blkMax256(fmaxf(v0, v1), scr);
    float e0 = __expf(v0 - M), e1 = __expf(v1 - M);
    float S = blkSum256(e0 + e1, scr);
    float r = 0.1f / S;
    float a0 = e0 * r, a1 = e1 * r;
    g_At[tid * KCAP + j]         = a0;
    g_At[(tid + 256) * KCAP + j] = a1;
    col[tid] = a0; col[tid + 256] = a1;
    __syncthreads();
    // lane-major layout for column j
    if (tid < 128) {
        int gg = tid >> 2, kq = tid & 3;
        int w = j >> 5, t = (j >> 3) & 3, jj = t >> 1, tpar = t & 1, nq = j & 7;
        int lane = nq * 4 + kq;
        int k0 = gg * 16 + 2 * kq;
        unsigned b0 = packhf(col[k0],     col[k0 + 1]);
        unsigned b1 = packhf(col[k0 + 8], col[k0 + 9]);
        unsigned base = (unsigned)((((gg * 16 + w) * 2 + jj) * 32 + lane) * 4 + tpar * 2);
        g_AtB[base]     = b0;
        g_AtB[base + 1] = b1;
    }
}

// ---------------- P2: fold iteration 0 ----------------
__global__ void __launch_bounds__(256) k_prep(const float* __restrict__ brun) {
    __shared__ float br[KCAP];
    __shared__ float sg[KCAP];
    __shared__ float scr[8];
    const int tid = threadIdx.x;
    const float invT = g_sc[0];
    float v0 = brun[tid], v1 = brun[tid + 256];
    br[tid] = v0; br[tid + 256] = v1;
    float M = blkMax256(fmaxf(v0, v1), scr);
    float e0 = __expf((v0 - M) * invT), e1 = __expf((v1 - M) * invT);
    float S = blkSum256(e0 + e1, scr);
    float is = 1.0f / S;
    sg[tid] = e0 * is; sg[tid + 256] = e1 * is;
    __syncthreads();
    const int j = blockIdx.x * 256 + tid;
    float u = 0.0f, w = 0.0f;
    #pragma unroll 8
    for (int k = 0; k < KCAP; k++) {
        float at = g_At[k * KCAP + j];
        u = fmaf(br[k], at, u);
        w = fmaf(sg[k], at, w);
    }
    g_u1[j] = br[j] + u;
    g_w1[j] = sg[j] + w;
}

// ---------------- P3: fused x@W.T + row sum-of-squares, single fp16 mma ----------------
#define SSTRIDE 20
__global__ void __launch_bounds__(256, 2) k_norm(const float* __restrict__ x,
                                                 const float* __restrict__ W, int B) {
    __shared__ unsigned XH[128 * SSTRIDE];
    __shared__ unsigned WH[128 * SSTRIDE];
    __shared__ float red2[128 * 2];

    const int tid  = threadIdx.x;
    const int lane = tid & 31;
    const int w    = tid >> 5;
    const int mrow = (w & 3) * 32;
    const int ncol = (w >> 2) * 64;
    const int row0 = blockIdx.x * 128;
    const int col0 = blockIdx.y * 128;

    const int srow = tid >> 1;
    const int soff = (tid & 1) * 16;
    const float* xp = x + (size_t)(row0 + srow) * DDIM + soff;
    const float* wp = W + (size_t)(col0 + srow) * DDIM + soff;
    const int sbase = srow * SSTRIDE + (tid & 1) * 8;

    float acc[2][8][4];
    #pragma unroll
    for (int mt = 0; mt < 2; mt++)
        #pragma unroll
        for (int nt = 0; nt < 8; nt++)
            #pragma unroll
            for (int q = 0; q < 4; q++) acc[mt][nt][q] = 0.0f;

    float4 rx[4], rw[4];
    #pragma unroll
    for (int i = 0; i < 4; i++) { rx[i] = *(const float4*)(xp + i * 4); rw[i] = *(const float4*)(wp + i * 4); }

    for (int kt = 0; kt < DDIM / 32; kt++) {
        __syncthreads();
        #pragma unroll
        for (int i = 0; i < 4; i++) {
            float4 v = rx[i];
            XH[sbase + i * 2]     = packhf(v.x, v.y);
            XH[sbase + i * 2 + 1] = packhf(v.z, v.w);
            float4 u = rw[i];
            WH[sbase + i * 2]     = packhf(u.x, u.y);
            WH[sbase + i * 2 + 1] = packhf(u.z, u.w);
        }
        __syncthreads();
        if (kt < DDIM / 32 - 1) {
            const float* xq = xp + (kt + 1) * 32;
            const float* wq = wp + (kt + 1) * 32;
            #pragma unroll
            for (int i = 0; i < 4; i++) { rx[i] = *(const float4*)(xq + i * 4); rw[i] = *(const float4*)(wq + i * 4); }
        }
        #pragma unroll
        for (int c = 0; c < 2; c++) {
            const int kb = c * 8 + (lane & 3);
            unsigned ah[2][4];
            #pragma unroll
            for (int mt = 0; mt < 2; mt++) {
                int ra = (mrow + mt * 16 + (lane >> 2)) * SSTRIDE;
                ah[mt][0] = XH[ra + kb];
                ah[mt][1] = XH[ra + 8 * SSTRIDE + kb];
                ah[mt][2] = XH[ra + kb + 4];
                ah[mt][3] = XH[ra + 8 * SSTRIDE + kb + 4];
            }
            #pragma unroll
            for (int nt = 0; nt < 8; nt++) {
                int rb = (ncol + nt * 8 + (lane >> 2)) * SSTRIDE;
                unsigned bh0 = WH[rb + kb], bh1 = WH[rb + kb + 4];
                #pragma unroll
                for (int mt = 0; mt < 2; mt++) {
                    MMA_F16(acc[mt][nt], ah[mt][0], ah[mt][1], ah[mt][2], ah[mt][3], bh0, bh1);
                }
            }
        }
    }

    #pragma unroll
    for (int mt = 0; mt < 2; mt++) {
        #pragma unroll
        for (int h = 0; h < 2; h++) {
            float s = 0.0f;
            #pragma unroll
            for (int nt = 0; nt < 8; nt++) {
                float a = acc[mt][nt][2 * h], b = acc[mt][nt][2 * h + 1];
                s = fmaf(a, a, fmaf(b, b, s));
            }
            s += __shfl_xor_sync(0xffffffffu, s, 1);
            s += __shfl_xor_sync(0xffffffffu, s, 2);
            if ((lane & 3) == 0) {
                int rloc = mrow + mt * 16 + (lane >> 2) + h * 8;
                red2[rloc * 2 + (w >> 2)] = s;
            }
        }
    }
    __syncthreads();
    if (tid < 128) {
        float s = red2[tid * 2] + red2[tid * 2 + 1];
        g_nsp[(size_t)blockIdx.y * B + row0 + tid] = s;
    }
}

// ---------------- P4: agreement ----------------
__global__ void k_agree(int B) {
    int i = blockIdx.x * 256 + threadIdx.x;
    if (i < B) {
        float c = g_sc[1];
        float ns = g_nsp[i] + g_nsp[B + i] + g_nsp[2 * B + i] + g_nsp[3 * B + i];
        ns = fmaxf(ns, 1e-10f);
        float sc2 = c * ns / (1.0f + c * ns);
        g_agr[i] = sc2 * sqrtf(ns);
    }
}

// ---------------- MAIN: 64 rows/block, barrier-free GEMM (B via LDG, A via f16 smem) ----------------
// smem: b_s[64][520] f32 | bh_s[64][260] u32 (f16x2 kpairs) | red[512] | agrs[64]
#define BHS 260
#define SMEM_MAIN_BYTES ((64 * PAD + 512 + 64) * 4 + 64 * BHS * 4)

__global__ void __launch_bounds__(512, 1) k_main(float* __restrict__ out) {
    extern __shared__ float sm[];
    float*    b_s  = sm;                              // [64][PAD]
    unsigned* bh   = (unsigned*)(sm + 64 * PAD);      // [64][BHS]
    float*    red  = (float*)(bh + 64 * BHS);         // [512]
    float*    agrs = red + 512;                       // [64]

    const int tid  = threadIdx.x;
    const int lane = tid & 31;
    const int wrp  = tid >> 5;               // 0..15 = n-stripe (32 cols)
    const int row0 = blockIdx.x * 64;
    const float invT = g_sc[0];

    const int r  = tid >> 3;                 // 0..63
    const int t8 = tid & 7;
    float* base = b_s + r * PAD + t8 * 4;
    unsigned* bhrow = bh + r * BHS + t8 * 2;

    if (tid < 64) agrs[tid] = g_agr[row0 + tid];
    float uj = g_u1[tid & 511];
    float wj = g_w1[tid & 511];
    __syncthreads();
    #pragma unroll 8
    for (int r2 = 0; r2 < 64; r2++)
        b_s[r2 * PAD + tid] = fmaf(agrs[r2], wj, uj);
    __syncthreads();

    // B fragment gmem base for this warp (uint4 units); gg stride = 1024 uint4
    const uint4* bbase = (const uint4*)g_AtB + (wrp * 2) * 32 + lane;

    for (int it = 0; it < 4; it++) {
        // ---- b += a * softmax(b/T); also write f16 copy to bh ----
        float mx = -3.4e38f;
        #pragma unroll
        for (int j = 0; j < 16; j++) {
            float4 v = *(const float4*)(base + j * 32);
            mx = fmaxf(mx, fmaxf(fmaxf(v.x, v.y), fmaxf(v.z, v.w)));
        }
        red[tid] = mx; __syncthreads();
        float m = red[r * 8];
        #pragma unroll
        for (int q = 1; q < 8; q++) m = fmaxf(m, red[r * 8 + q]);
        __syncthreads();
        float s = 0.0f;
        #pragma unroll
        for (int j = 0; j < 16; j++) {
            float4 v = *(const float4*)(base + j * 32);
            s += __expf((v.x - m) * invT) + __expf((v.y - m) * invT)
               + __expf((v.z - m) * invT) + __expf((v.w - m) * invT);
        }
        red[tid] = s; __syncthreads();
        float S = red[r * 8];
        #pragma unroll
        for (int q = 1; q < 8; q++) S += red[r * 8 + q];
        float aS = agrs[r] / S;
        #pragma unroll
        for (int j = 0; j < 16; j++) {
            float4 v = *(const float4*)(base + j * 32);
            v.x = fmaf(aS, __expf((v.x - m) * invT), v.x);
            v.y = fmaf(aS, __expf((v.y - m) * invT), v.y);
            v.z = fmaf(aS, __expf((v.z - m) * invT), v.z);
            v.w = fmaf(aS, __expf((v.w - m) * invT), v.w);
            *(float4*)(base + j * 32) = v;
            *(uint2*)(bhrow + j * 16) = make_uint2(packhf(v.x, v.y), packhf(v.z, v.w));
        }
        __syncthreads();   // bh ready for all warps

        // ---- d = b @ AtH: zero-barrier GEMM (B from L2 via LDG, A from bh) ----
        float acc[4][4][4];
        #pragma unroll
        for (int mt = 0; mt < 4; mt++)
            #pragma unroll
            for (int nt = 0; nt < 4; nt++)
                #pragma unroll
                for (int q = 0; q < 4; q++) acc[mt][nt][q] = 0.0f;

        uint4 B0 = bbase[0], B1 = bbase[32];
        #pragma unroll 4
        for (int gg = 0; gg < 32; gg++) {
            uint4 C0, C1;
            if (gg < 31) {
                const uint4* nb = bbase + (gg + 1) * 1024;
                C0 = nb[0]; C1 = nb[32];
            }
            const int kb = gg * 8 + (lane & 3);
            #pragma unroll
            for (int mt = 0; mt < 4; mt++) {
                int ra = (mt * 16 + (lane >> 2)) * BHS + kb;
                unsigned a0 = bh[ra];
                unsigned a1 = bh[ra + 8 * BHS];
                unsigned a2 = bh[ra + 4];
                unsigned a3 = bh[ra + 8 * BHS + 4];
                MMA_F16(acc[mt][0], a0, a1, a2, a3, B0.x, B0.y);
                MMA_F16(acc[mt][1], a0, a1, a2, a3, B0.z, B0.w);
                MMA_F16(acc[mt][2], a0, a1, a2, a3, B1.x, B1.y);
                MMA_F16(acc[mt][3], a0, a1, a2, a3, B1.z, B1.w);
            }
            B0 = C0; B1 = C1;
        }

        // ---- b += d ----
        #pragma unroll
        for (int mt = 0; mt < 4; mt++) {
            int row = mt * 16 + (lane >> 2);
            #pragma unroll
            for (int nt = 0; nt < 4; nt++) {
                int col = wrp * 32 + nt * 8 + 2 * (lane & 3);
                float* p = b_s + row * PAD + col;
                p[0]           += acc[mt][nt][0];
                p[1]           += acc[mt][nt][1];
                p[8 * PAD]     += acc[mt][nt][2];
                p[8 * PAD + 1] += acc[mt][nt][3];
            }
        }
        __syncthreads();   // b_s updated before next softmax / final
    }

    // ---- theta = softmax(b/T) -> out ----
    {
        float mx = -3.4e38f;
        #pragma unroll
        for (int j = 0; j < 16; j++) {
            float4 v = *(const float4*)(base + j * 32);
            mx = fmaxf(mx, fmaxf(fmaxf(v.x, v.y), fmaxf(v.z, v.w)));
        }
        red[tid] = mx; __syncthreads();
        float m = red[r * 8];
        #pragma unroll
        for (int q = 1; q < 8; q++) m = fmaxf(m, red[r * 8 + q]);
        __syncthreads();
        float s = 0.0f;
        #pragma unroll
        for (int j = 0; j < 16; j++) {
            float4 v = *(const float4*)(base + j * 32);
            s += __expf((v.x - m) * invT) + __expf((v.y - m) * invT)
               + __expf((v.z - m) * invT) + __expf((v.w - m) * invT);
        }
        red[tid] = s; __syncthreads();
        float S = red[r * 8];
        #pragma unroll
        for (int q = 1; q < 8; q++) S += red[r * 8 + q];
        float iS = 1.0f / S;
        float* op = out + (size_t)(row0 + r) * KCAP + t8 * 4;
        #pragma unroll
        for (int j = 0; j < 16; j++) {
            float4 v = *(const float4*)(base + j * 32);
            float4 o;
            o.x = __expf((v.x - m) * invT) * iS;
            o.y = __expf((v.y - m) * invT) * iS;
            o.z = __expf((v.z - m) * invT) * iS;
            o.w = __expf((v.w - m) * invT) * iS;
            *(float4*)(op + j * 32) = o;
        }
    }
}

// ---------------- launcher ----------------
extern "C" void kernel_launch(void* const* d_in, const int* in_sizes, int n_in,
                              void* d_out, int out_size) {
    const float* x    = (const float*)d_in[0];
    const float* W    = (const float*)d_in[1];
    const float* A    = (const float*)d_in[2];
    const float* lT   = (const float*)d_in[3];
    const float* lc   = (const float*)d_in[4];
    const float* brun = (const float*)d_in[5];
    const void*  temp = d_in[6];
    const int B = in_sizes[0] / DDIM;   // 16384

    cudaFuncSetAttribute(k_main, cudaFuncAttributeMaxDynamicSharedMemorySize,
                         SMEM_MAIN_BYTES);

    k_scalars<<<1, 32>>>(lT, lc, temp);
    k_adiff<<<KCAP, 256>>>(A);
    k_prep<<<2, 256>>>(brun);
    k_norm<<<dim3(B / 128, 4), 256>>>(x, W, B);
    k_agree<<<(B + 255) / 256, 256>>>(B);
    k_main<<<B / 64, 512, SMEM_MAIN_BYTES>>>((float*)d_out);
}

// round 12
// speedup vs baseline: 1.9011x; 1.1571x over previous
#include <cuda_runtime.h>
#include <cuda_fp16.h>
#include <cstdint>

#define KCAP 512
#define DDIM 1024
#define BMAX 16384
#define PAD  520

// ---------------- device scratch (no allocations allowed) ----------------
__device__ __align__(16) float g_At[KCAP * KCAP];   // fp32 0.1*A_diff^T (for k_prep)
// Lane-major f16 At for k_main B fragments (see R11)
__device__ __align__(16) unsigned g_AtB[32 * 16 * 2 * 32 * 4];
// x as mma A-fragments: [(rt*64+gg)*32+lane] uint4 {a0,a1,a2,a3}
//   rt = row-tile of 16 (1024), gg = k16 chunk (64), r = lane>>2, k0 = gg*16+2*(lane&3)
//   a0 = x[rt*16+r][k0,k0+1], a1 = +8 row, a2 = k0+8, a3 = +8 row k0+8   (f16x2)
__device__ uint4 g_xB[1024 * 64 * 32];
// W as mma B-fragments: [(ctp*64+gg)*32+lane] uint4 {bh0_e, bh1_e, bh0_o, bh1_o}
//   ctp = col-pair-tile of 16 (32), n_e = ctp*16 + (lane>>2), n_o = +8
__device__ uint4 g_wB[32 * 64 * 32];
__device__ float g_nsp[4 * BMAX];
__device__ float g_agr[BMAX];
__device__ __align__(16) float g_u1[KCAP];
__device__ __align__(16) float g_w1[KCAP];
__device__ float g_sc[2];                            // {1/T_eff, c}

// ---------------- helpers ----------------
__device__ __forceinline__ float blkMax256(float v, float* sc) {
    #pragma unroll
    for (int o = 16; o > 0; o >>= 1) v = fmaxf(v, __shfl_xor_sync(0xffffffffu, v, o));
    if ((threadIdx.x & 31) == 0) sc[threadIdx.x >> 5] = v;
    __syncthreads();
    float r = sc[0];
    #pragma unroll
    for (int i = 1; i < 8; i++) r = fmaxf(r, sc[i]);
    __syncthreads();
    return r;
}
__device__ __forceinline__ float blkSum256(float v, float* sc) {
    #pragma unroll
    for (int o = 16; o > 0; o >>= 1) v += __shfl_xor_sync(0xffffffffu, v, o);
    if ((threadIdx.x & 31) == 0) sc[threadIdx.x >> 5] = v;
    __syncthreads();
    float r = sc[0];
    #pragma unroll
    for (int i = 1; i < 8; i++) r += sc[i];
    __syncthreads();
    return r;
}
__device__ __forceinline__ unsigned packhf(float lo, float hi) {
    unsigned r;
    asm("cvt.rn.f16x2.f32 %0, %1, %2;" : "=r"(r) : "f"(hi), "f"(lo));
    return r;
}

#define MMA_F16(c, a0, a1, a2, a3, b0, b1)                                             \
    asm volatile(                                                                       \
        "mma.sync.aligned.m16n8k16.row.col.f32.f16.f16.f32 "                            \
        "{%0,%1,%2,%3},{%4,%5,%6,%7},{%8,%9},{%0,%1,%2,%3};"                            \
        : "+f"((c)[0]), "+f"((c)[1]), "+f"((c)[2]), "+f"((c)[3])                        \
        : "r"(a0), "r"(a1), "r"(a2), "r"(a3), "r"(b0), "r"(b1))

// ---------------- P0: scalars ----------------
__global__ void k_scalars(const float* __restrict__ lT, const float* __restrict__ lc,
                          const void* __restrict__ tp) {
    if (threadIdx.x == 0) {
        unsigned w = *(const unsigned*)tp;
        float ft = __uint_as_float(w);
        float tempv = (fabsf(ft) > 1e-30f && fabsf(ft) < 1e30f) ? ft : (float)(int)w;
        float T = fminf(fmaxf(expf(lT[0]) * tempv, 0.05f), 10.0f);
        g_sc[0] = 1.0f / T;
        g_sc[1] = fminf(fmaxf(expf(lc[0]), 0.01f), 10.0f);
    }
}

// ---------------- P1: symmetric softmax -> At fp32 + lane-major f16 ----------------
__global__ void __launch_bounds__(256) k_adiff(const float* __restrict__ A) {
    __shared__ float scr[8];
    __shared__ float col[KCAP];
    const int j = blockIdx.x, tid = threadIdx.x;
    float v0 = 0.5f * (A[j * KCAP + tid]       + A[tid * KCAP + j]);
    float v1 = 0.5f * (A[j * KCAP + tid + 256] + A[(tid + 256) * KCAP + j]);
    float M = blkMax256(fmaxf(v0, v1), scr);
    float e0 = __expf(v0 - M), e1 = __expf(v1 - M);
    float S = blkSum256(e0 + e1, scr);
    float r = 0.1f / S;
    float a0 = e0 * r, a1 = e1 * r;
    g_At[tid * KCAP + j]         = a0;
    g_At[(tid + 256) * KCAP + j] = a1;
    col[tid] = a0; col[tid + 256] = a1;
    __syncthreads();
    if (tid < 128) {
        int gg = tid >> 2, kq = tid & 3;
        int w = j >> 5, t = (j >> 3) & 3, jj = t >> 1, tpar = t & 1, nq = j & 7;
        int lane = nq * 4 + kq;
        int k0 = gg * 16 + 2 * kq;
        unsigned b0 = packhf(col[k0],     col[k0 + 1]);
        unsigned b1 = packhf(col[k0 + 8], col[k0 + 9]);
        unsigned base = (unsigned)((((gg * 16 + w) * 2 + jj) * 32 + lane) * 4 + tpar * 2);
        g_AtB[base]     = b0;
        g_AtB[base + 1] = b1;
    }
}

// ---------------- P2: fold iteration 0 ----------------
__global__ void __launch_bounds__(256) k_prep(const float* __restrict__ brun) {
    __shared__ float br[KCAP];
    __shared__ float sg[KCAP];
    __shared__ float scr[8];
    const int tid = threadIdx.x;
    const float invT = g_sc[0];
    float v0 = brun[tid], v1 = brun[tid + 256];
    br[tid] = v0; br[tid + 256] = v1;
    float M = blkMax256(fmaxf(v0, v1), scr);
    float e0 = __expf((v0 - M) * invT), e1 = __expf((v1 - M) * invT);
    float S = blkSum256(e0 + e1, scr);
    float is = 1.0f / S;
    sg[tid] = e0 * is; sg[tid + 256] = e1 * is;
    __syncthreads();
    const int j = blockIdx.x * 256 + tid;
    float u = 0.0f, w = 0.0f;
    #pragma unroll 8
    for (int k = 0; k < KCAP; k++) {
        float at = g_At[k * KCAP + j];
        u = fmaf(br[k], at, u);
        w = fmaf(sg[k], at, w);
    }
    g_u1[j] = br[j] + u;
    g_w1[j] = sg[j] + w;
}

// ---------------- P3a: x -> A-fragment layout (fp16) ----------------
#define CXS 1032
__global__ void __launch_bounds__(256) k_convx(const float* __restrict__ x) {
    extern __shared__ float xs[];   // [16][CXS]
    const int rt = blockIdx.x, tid = threadIdx.x;
    for (int i = tid; i < 16 * 256; i += 256) {
        int row = i >> 8, c4 = (i & 255) * 4;
        *(float4*)&xs[row * CXS + c4] =
            *(const float4*)&x[(size_t)(rt * 16 + row) * DDIM + c4];
    }
    __syncthreads();
    #pragma unroll
    for (int i = 0; i < 8; i++) {
        int f = i * 256 + tid;
        int gg = f >> 5, lane = f & 31;
        int r = lane >> 2, k0 = gg * 16 + 2 * (lane & 3);
        uint4 v;
        v.x = packhf(xs[r * CXS + k0],           xs[r * CXS + k0 + 1]);
        v.y = packhf(xs[(r + 8) * CXS + k0],     xs[(r + 8) * CXS + k0 + 1]);
        v.z = packhf(xs[r * CXS + k0 + 8],       xs[r * CXS + k0 + 9]);
        v.w = packhf(xs[(r + 8) * CXS + k0 + 8], xs[(r + 8) * CXS + k0 + 9]);
        g_xB[(size_t)(rt * 64 + gg) * 32 + lane] = v;
    }
}

// ---------------- P3b: W -> B-fragment layout (fp16) ----------------
__global__ void __launch_bounds__(256) k_convw(const float* __restrict__ W) {
    extern __shared__ float xs[];   // [16][CXS]
    const int ctp = blockIdx.x, tid = threadIdx.x;
    for (int i = tid; i < 16 * 256; i += 256) {
        int row = i >> 8, c4 = (i & 255) * 4;
        *(float4*)&xs[row * CXS + c4] =
            *(const float4*)&W[(size_t)(ctp * 16 + row) * DDIM + c4];
    }
    __syncthreads();
    #pragma unroll
    for (int i = 0; i < 8; i++) {
        int f = i * 256 + tid;
        int gg = f >> 5, lane = f & 31;
        int nl = lane >> 2, k0 = gg * 16 + 2 * (lane & 3);
        uint4 v;
        v.x = packhf(xs[nl * CXS + k0],           xs[nl * CXS + k0 + 1]);
        v.y = packhf(xs[nl * CXS + k0 + 8],       xs[nl * CXS + k0 + 9]);
        v.z = packhf(xs[(nl + 8) * CXS + k0],     xs[(nl + 8) * CXS + k0 + 1]);
        v.w = packhf(xs[(nl + 8) * CXS + k0 + 8], xs[(nl + 8) * CXS + k0 + 9]);
        g_wB[(size_t)(ctp * 64 + gg) * 32 + lane] = v;
    }
}

// ---------------- P3c: barrier-free GEMM + row sum-of-squares ----------------
__global__ void __launch_bounds__(256, 2) k_norm(int B) {
    __shared__ float red2[128 * 2];
    const int tid  = threadIdx.x;
    const int lane = tid & 31;
    const int w    = tid >> 5;
    const int mrow = (w & 3) * 32;
    const int cg   = w >> 2;                 // 0,1 col stripe of 64
    const int yg   = blockIdx.y;

    // A fragments: rt = blockIdx.x*8 + (w&3)*2 + mt ; stride per rt = 2048 uint4
    const uint4* xb = g_xB + ((size_t)(blockIdx.x * 8 + (w & 3) * 2) * 64) * 32 + lane;
    // B fragments: ctp = yg*8 + cg*4 + p ; stride per ctp = 2048 uint4
    const uint4* wb = g_wB + ((size_t)(yg * 8 + cg * 4) * 64) * 32 + lane;

    float acc[2][8][4];
    #pragma unroll
    for (int mt = 0; mt < 2; mt++)
        #pragma unroll
        for (int nt = 0; nt < 8; nt++)
            #pragma unroll
            for (int q = 0; q < 4; q++) acc[mt][nt][q] = 0.0f;

    uint4 A[2], Bv[4];
    #pragma unroll
    for (int mt = 0; mt < 2; mt++) A[mt] = xb[mt * 2048];
    #pragma unroll
    for (int p = 0; p < 4; p++) Bv[p] = wb[p * 2048];

    #pragma unroll 4
    for (int gg = 0; gg < 64; gg++) {
        uint4 A2[2], B2[4];
        if (gg < 63) {
            const uint4* xn = xb + (gg + 1) * 32;
            const uint4* wn = wb + (gg + 1) * 32;
            #pragma unroll
            for (int mt = 0; mt < 2; mt++) A2[mt] = xn[mt * 2048];
            #pragma unroll
            for (int p = 0; p < 4; p++) B2[p] = wn[p * 2048];
        }
        #pragma unroll
        for (int mt = 0; mt < 2; mt++) {
            #pragma unroll
            for (int p = 0; p < 4; p++) {
                MMA_F16(acc[mt][2 * p],     A[mt].x, A[mt].y, A[mt].z, A[mt].w, Bv[p].x, Bv[p].y);
                MMA_F16(acc[mt][2 * p + 1], A[mt].x, A[mt].y, A[mt].z, A[mt].w, Bv[p].z, Bv[p].w);
            }
        }
        #pragma unroll
        for (int mt = 0; mt < 2; mt++) A[mt] = A2[mt];
        #pragma unroll
        for (int p = 0; p < 4; p++) Bv[p] = B2[p];
    }

    #pragma unroll
    for (int mt = 0; mt < 2; mt++) {
        #pragma unroll
        for (int h = 0; h < 2; h++) {
            float s = 0.0f;
            #pragma unroll
            for (int nt = 0; nt < 8; nt++) {
                float a = acc[mt][nt][2 * h], b = acc[mt][nt][2 * h + 1];
                s = fmaf(a, a, fmaf(b, b, s));
            }
            s += __shfl_xor_sync(0xffffffffu, s, 1);
            s += __shfl_xor_sync(0xffffffffu, s, 2);
            if ((lane & 3) == 0) {
                int rloc = mrow + mt * 16 + (lane >> 2) + h * 8;
                red2[rloc * 2 + cg] = s;
            }
        }
    }
    __syncthreads();
    if (tid < 128) {
        float s = red2[tid * 2] + red2[tid * 2 + 1];
        g_nsp[(size_t)yg * B + blockIdx.x * 128 + tid] = s;
    }
}

// ---------------- P4: agreement ----------------
__global__ void k_agree(int B) {
    int i = blockIdx.x * 256 + threadIdx.x;
    if (i < B) {
        float c = g_sc[1];
        float ns = g_nsp[i] + g_nsp[B + i] + g_nsp[2 * B + i] + g_nsp[3 * B + i];
        ns = fmaxf(ns, 1e-10f);
        float sc2 = c * ns / (1.0f + c * ns);
        g_agr[i] = sc2 * sqrtf(ns);
    }
}

// ---------------- MAIN: unchanged from R11 ----------------
#define BHS 260
#define SMEM_MAIN_BYTES ((64 * PAD + 512 + 64) * 4 + 64 * BHS * 4)

__global__ void __launch_bounds__(512, 1) k_main(float* __restrict__ out) {
    extern __shared__ float sm[];
    float*    b_s  = sm;                              // [64][PAD]
    unsigned* bh   = (unsigned*)(sm + 64 * PAD);      // [64][BHS]
    float*    red  = (float*)(bh + 64 * BHS);         // [512]
    float*    agrs = red + 512;                       // [64]

    const int tid  = threadIdx.x;
    const int lane = tid & 31;
    const int wrp  = tid >> 5;
    const int row0 = blockIdx.x * 64;
    const float invT = g_sc[0];

    const int r  = tid >> 3;
    const int t8 = tid & 7;
    float* base = b_s + r * PAD + t8 * 4;
    unsigned* bhrow = bh + r * BHS + t8 * 2;

    if (tid < 64) agrs[tid] = g_agr[row0 + tid];
    float uj = g_u1[tid & 511];
    float wj = g_w1[tid & 511];
    __syncthreads();
    #pragma unroll 8
    for (int r2 = 0; r2 < 64; r2++)
        b_s[r2 * PAD + tid] = fmaf(agrs[r2], wj, uj);
    __syncthreads();

    const uint4* bbase = (const uint4*)g_AtB + (wrp * 2) * 32 + lane;

    for (int it = 0; it < 4; it++) {
        float mx = -3.4e38f;
        #pragma unroll
        for (int j = 0; j < 16; j++) {
            float4 v = *(const float4*)(base + j * 32);
            mx = fmaxf(mx, fmaxf(fmaxf(v.x, v.y), fmaxf(v.z, v.w)));
        }
        red[tid] = mx; __syncthreads();
        float m = red[r * 8];
        #pragma unroll
        for (int q = 1; q < 8; q++) m = fmaxf(m, red[r * 8 + q]);
        __syncthreads();
        float s = 0.0f;
        #pragma unroll
        for (int j = 0; j < 16; j++) {
            float4 v = *(const float4*)(base + j * 32);
            s += __expf((v.x - m) * invT) + __expf((v.y - m) * invT)
               + __expf((v.z - m) * invT) + __expf((v.w - m) * invT);
        }
        red[tid] = s; __syncthreads();
        float S = red[r * 8];
        #pragma unroll
        for (int q = 1; q < 8; q++) S += red[r * 8 + q];
        float aS = agrs[r] / S;
        #pragma unroll
        for (int j = 0; j < 16; j++) {
            float4 v = *(const float4*)(base + j * 32);
            v.x = fmaf(aS, __expf((v.x - m) * invT), v.x);
            v.y = fmaf(aS, __expf((v.y - m) * invT), v.y);
            v.z = fmaf(aS, __expf((v.z - m) * invT), v.z);
            v.w = fmaf(aS, __expf((v.w - m) * invT), v.w);
            *(float4*)(base + j * 32) = v;
            *(uint2*)(bhrow + j * 16) = make_uint2(packhf(v.x, v.y), packhf(v.z, v.w));
        }
        __syncthreads();

        float acc[4][4][4];
        #pragma unroll
        for (int mt = 0; mt < 4; mt++)
            #pragma unroll
            for (int nt = 0; nt < 4; nt++)
                #pragma unroll
                for (int q = 0; q < 4; q++) acc[mt][nt][q] = 0.0f;

        uint4 B0 = bbase[0], B1 = bbase[32];
        #pragma unroll 4
        for (int gg = 0; gg < 32; gg++) {
            uint4 C0, C1;
            if (gg < 31) {
                const uint4* nb = bbase + (gg + 1) * 1024;
                C0 = nb[0]; C1 = nb[32];
            }
            const int kb = gg * 8 + (lane & 3);
            #pragma unroll
            for (int mt = 0; mt < 4; mt++) {
                int ra = (mt * 16 + (lane >> 2)) * BHS + kb;
                unsigned a0 = bh[ra];
                unsigned a1 = bh[ra + 8 * BHS];
                unsigned a2 = bh[ra + 4];
                unsigned a3 = bh[ra + 8 * BHS + 4];
                MMA_F16(acc[mt][0], a0, a1, a2, a3, B0.x, B0.y);
                MMA_F16(acc[mt][1], a0, a1, a2, a3, B0.z, B0.w);
                MMA_F16(acc[mt][2], a0, a1, a2, a3, B1.x, B1.y);
                MMA_F16(acc[mt][3], a0, a1, a2, a3, B1.z, B1.w);
            }
            B0 = C0; B1 = C1;
        }

        #pragma unroll
        for (int mt = 0; mt < 4; mt++) {
            int row = mt * 16 + (lane >> 2);
            #pragma unroll
            for (int nt = 0; nt < 4; nt++) {
                int col = wrp * 32 + nt * 8 + 2 * (lane & 3);
                float* p = b_s + row * PAD + col;
                p[0]           += acc[mt][nt][0];
                p[1]           += acc[mt][nt][1];
                p[8 * PAD]     += acc[mt][nt][2];
                p[8 * PAD + 1] += acc[mt][nt][3];
            }
        }
        __syncthreads();
    }

    {
        float mx = -3.4e38f;
        #pragma unroll
        for (int j = 0; j < 16; j++) {
            float4 v = *(const float4*)(base + j * 32);
            mx = fmaxf(mx, fmaxf(fmaxf(v.x, v.y), fmaxf(v.z, v.w)));
        }
        red[tid] = mx; __syncthreads();
        float m = red[r * 8];
        #pragma unroll
        for (int q = 1; q < 8; q++) m = fmaxf(m, red[r * 8 + q]);
        __syncthreads();
        float s = 0.0f;
        #pragma unroll
        for (int j = 0; j < 16; j++) {
            float4 v = *(const float4*)(base + j * 32);
            s += __expf((v.x - m) * invT) + __expf((v.y - m) * invT)
               + __expf((v.z - m) * invT) + __expf((v.w - m) * invT);
        }
        red[tid] = s; __syncthreads();
        float S = red[r * 8];
        #pragma unroll
        for (int q = 1; q < 8; q++) S += red[r * 8 + q];
        float iS = 1.0f / S;
        float* op = out + (size_t)(row0 + r) * KCAP + t8 * 4;
        #pragma unroll
        for (int j = 0; j < 16; j++) {
            float4 v = *(const float4*)(base + j * 32);
            float4 o;
            o.x = __expf((v.x - m) * invT) * iS;
            o.y = __expf((v.y - m) * invT) * iS;
            o.z = __expf((v.z - m) * invT) * iS;
            o.w = __expf((v.w - m) * invT) * iS;
            *(float4*)(op + j * 32) = o;
        }
    }
}

// ---------------- launcher ----------------
extern "C" void kernel_launch(void* const* d_in, const int* in_sizes, int n_in,
                              void* d_out, int out_size) {
    const float* x    = (const float*)d_in[0];
    const float* W    = (const float*)d_in[1];
    const float* A    = (const float*)d_in[2];
    const float* lT   = (const float*)d_in[3];
    const float* lc   = (const float*)d_in[4];
    const float* brun = (const float*)d_in[5];
    const void*  temp = d_in[6];
    const int B = in_sizes[0] / DDIM;   // 16384
    const int CONV_SMEM = 16 * CXS * 4;

    cudaFuncSetAttribute(k_main, cudaFuncAttributeMaxDynamicSharedMemorySize,
                         SMEM_MAIN_BYTES);
    cudaFuncSetAttribute(k_convx, cudaFuncAttributeMaxDynamicSharedMemorySize,
                         CONV_SMEM);
    cudaFuncSetAttribute(k_convw, cudaFuncAttributeMaxDynamicSharedMemorySize,
                         CONV_SMEM);

    k_scalars<<<1, 32>>>(lT, lc, temp);
    k_adiff<<<KCAP, 256>>>(A);
    k_prep<<<2, 256>>>(brun);
    k_convx<<<B / 16, 256, CONV_SMEM>>>(x);
    k_convw<<<KCAP / 16, 256, CONV_SMEM>>>(W);
    k_norm<<<dim3(B / 128, 4), 256>>>(B);
    k_agree<<<(B + 255) / 256, 256>>>(B);
    k_main<<<B / 64, 512, SMEM_MAIN_BYTES>>>((float*)d_out);
}